// round 1
// baseline (speedup 1.0000x reference)
#include <cuda_runtime.h>
#include <math.h>

#define Nn   300
#define Tt   16384
#define WINw 1024
#define Rr   16
#define ODORo 16
#define DTc  0.2f

#define BM 64
#define BT 64
#define BK 16
#define WPAD 68   // 64 + 4 pad, keeps 16B alignment of rows (68*4=272 bytes)

// scratch for G = A_mu @ fr, A_lv @ fr  (300 x 1024 each)
__device__ float g_Gmu[Nn * WINw];
__device__ float g_Glv[Nn * WINw];

// ---------------------------------------------------------------------------
// K0: sensory_input S[n,t] = mask[n] * (dot(odor[t,:], W_enc[n,:]) + b_enc[n])
// grid: (T/256, N), block 256. Writes coalesced along t.
// ---------------------------------------------------------------------------
__global__ void k_sensory(const float* __restrict__ odor,
                          const float* __restrict__ Wenc,
                          const float* __restrict__ benc,
                          const float* __restrict__ mask,
                          float* __restrict__ S)
{
    int t = blockIdx.x * blockDim.x + threadIdx.x;
    int n = blockIdx.y;
    if (t >= Tt) return;
    float w[ODORo];
#pragma unroll
    for (int k = 0; k < ODORo; k++) w[k] = __ldg(&Wenc[n * ODORo + k]);
    float acc = __ldg(&benc[n]);
    const float* orow = odor + (size_t)t * ODORo;
#pragma unroll
    for (int k = 0; k < ODORo; k++) acc += orow[k] * w[k];
    S[(size_t)n * Tt + t] = acc * __ldg(&mask[n]);
}

// ---------------------------------------------------------------------------
// Fused dual-matrix GEMM:  C1 = W1 @ X,  C2 = W2 @ X   (M=K=300, cols=tcols)
// MODE 0: write raw C1 -> oa[m*tcols+t], C2 -> ob  (stage A: G matrices)
// MODE 1: mu = C1 + Gmu[m, t>>4]; lv = C2 + Glv[m, t>>4];
//         sample = mu + exp(0.5 lv)*eps;  oa=mu, ob=lv, oc=sample
// MODE 2: rec = W_c@relu(X) + W_e@X (C1 uses relu'd X);
//         mu_v = s + a*( -s + rec + S + bias ); ca = softplus(aw*s+ab)
//         oa=rec, ob=mu_v, oc=ca
// ---------------------------------------------------------------------------
template <int MODE>
__global__ void k_gemm(const float* __restrict__ W1,
                       const float* __restrict__ W2,
                       const float* __restrict__ X, int xstride, int tcols,
                       const float* __restrict__ gmu,
                       const float* __restrict__ glv,
                       const float* __restrict__ eps,
                       const float* __restrict__ sample,
                       const float* __restrict__ S,
                       const float* __restrict__ tau,
                       const float* __restrict__ bias,
                       const float* __restrict__ aw,
                       const float* __restrict__ ab,
                       float* __restrict__ oa,
                       float* __restrict__ ob,
                       float* __restrict__ oc)
{
    __shared__ __align__(16) float W1s[BK][WPAD];
    __shared__ __align__(16) float W2s[BK][WPAD];
    __shared__ __align__(16) float Xs[BK][BT];

    const int tid = threadIdx.x;            // 256 threads
    const int tx = tid & 15;                 // t sub-tile
    const int ty = tid >> 4;                 // m sub-tile
    const int t0 = blockIdx.x * BT;
    const int m0 = blockIdx.y * BM;

    float acc1[4][4] = {{0}}, acc2[4][4] = {{0}};

    for (int kk = 0; kk < Nn; kk += BK) {
        // ---- load W tiles, transposed to [k][m]
        {
            int kl = tid & 15;
            int ml = tid >> 4;   // 0..15
#pragma unroll
            for (int p = 0; p < 4; p++) {
                int mloc = ml + p * 16;
                int m = m0 + mloc;
                int k = kk + kl;
                float v1 = 0.f, v2 = 0.f;
                if (m < Nn && k < Nn) {
                    v1 = W1[(size_t)m * Nn + k];
                    v2 = W2[(size_t)m * Nn + k];
                }
                W1s[kl][mloc] = v1;
                W2s[kl][mloc] = v2;
            }
        }
        // ---- load X tile [k][t], coalesced along t
        {
            int tl = tid & 63;
            int kb = tid >> 6;   // 0..3
#pragma unroll
            for (int p = 0; p < 4; p++) {
                int kloc = kb + p * 4;
                int k = kk + kloc;
                float v = 0.f;
                if (k < Nn) v = X[(size_t)k * xstride + t0 + tl];
                Xs[kloc][tl] = v;
            }
        }
        __syncthreads();

#pragma unroll
        for (int k = 0; k < BK; k++) {
            float4 bq  = *(const float4*)&Xs[k][tx * 4];
            float4 a1q = *(const float4*)&W1s[k][ty * 4];
            float4 a2q = *(const float4*)&W2s[k][ty * 4];
            float bv[4]  = {bq.x, bq.y, bq.z, bq.w};
            float a1v[4] = {a1q.x, a1q.y, a1q.z, a1q.w};
            float a2v[4] = {a2q.x, a2q.y, a2q.z, a2q.w};
            if (MODE == 2) {
                float rv[4];
#pragma unroll
                for (int j = 0; j < 4; j++) rv[j] = fmaxf(bv[j], 0.f);
#pragma unroll
                for (int i = 0; i < 4; i++)
#pragma unroll
                    for (int j = 0; j < 4; j++) {
                        acc1[i][j] += a1v[i] * rv[j];   // W_c @ relu(x)
                        acc2[i][j] += a2v[i] * bv[j];   // W_e @ x
                    }
            } else {
#pragma unroll
                for (int i = 0; i < 4; i++)
#pragma unroll
                    for (int j = 0; j < 4; j++) {
                        acc1[i][j] += a1v[i] * bv[j];
                        acc2[i][j] += a2v[i] * bv[j];
                    }
            }
        }
        __syncthreads();
    }

    // ---- epilogue
#pragma unroll
    for (int i = 0; i < 4; i++) {
        int m = m0 + ty * 4 + i;
        if (m >= Nn) break;
#pragma unroll
        for (int j = 0; j < 4; j++) {
            int t = t0 + tx * 4 + j;
            size_t idx = (size_t)m * tcols + t;
            if (MODE == 0) {
                oa[idx] = acc1[i][j];
                ob[idx] = acc2[i][j];
            } else if (MODE == 1) {
                size_t gi = (size_t)m * WINw + (t >> 4);
                float mu = acc1[i][j] + gmu[gi];
                float lv = acc2[i][j] + glv[gi];
                float sm = mu + expf(0.5f * lv) * eps[idx];
                oa[idx] = mu;
                ob[idx] = lv;
                oc[idx] = sm;
            } else { // MODE 2
                float s   = sample[idx];
                float rec = acc1[i][j] + acc2[i][j];
                float alpha = DTc / fmaxf(__ldg(&tau[m]), DTc);
                float muv = s + alpha * (rec - s + S[idx] + __ldg(&bias[m]));
                float z = __ldg(&aw[m]) * s + __ldg(&ab[m]);
                float ca = fmaxf(z, 0.f) + log1pf(expf(-fabsf(z)));
                oa[idx] = rec;
                ob[idx] = muv;
                oc[idx] = ca;
            }
        }
    }
}

// ---------------------------------------------------------------------------
// K3: exponential calcium filter.  decay = exp(-DT/max(ctau,DT)) = e^-1 here,
// so a 64-step lookback reconstructs the carry to < 1e-27 relative.
// One block per neuron, 256 threads x 64-element chunks, smem transposed
// [64][257] so both scan and I/O phases are bank-conflict-free.
// ---------------------------------------------------------------------------
__global__ void k_scan(const float* __restrict__ ca,
                       const float* __restrict__ ffull,
                       const float* __restrict__ fls,
                       const float* __restrict__ flsh,
                       const float* __restrict__ ctau,
                       float* __restrict__ o_cal,
                       float* __restrict__ o_fl)
{
    extern __shared__ float buf[];            // [64][257]
    const int n = blockIdx.x;
    const int tid = threadIdx.x;              // 256
    const int C = Tt / 256;                   // 64

    const float* x = ca + (size_t)n * Tt;
    // transposed load: global i -> buf[(i%64)*257 + i/64]
    for (int i = tid; i < Tt; i += 256)
        buf[(i & 63) * 257 + (i >> 6)] = x[i];

    float fscale = __ldg(&fls[n]);
    float fshift = __ldg(&flsh[n]);
    float init = (__ldg(&ffull[(size_t)n * Tt]) - fshift) / fscale;
    float decay = expf(-DTc / fmaxf(__ldg(&ctau[n]), DTc));
    __syncthreads();

    const int start = tid * C;
    int lb = start - 64;
    float c;
    int s0;
    if (lb <= 0) { c = init; s0 = 0; }
    else         { c = 0.f;  s0 = lb; }
    for (int s = s0; s < start; s++) {
        float xv = buf[(s & 63) * 257 + (s >> 6)];
        c = (s == 0) ? (c + xv) : (decay * c + xv);
    }
    __syncthreads();
    // in-place scan of own chunk
    for (int t = start; t < start + C; t++) {
        int a = (t & 63) * 257 + (t >> 6);
        float xv = buf[a];
        c = (t == 0) ? (c + xv) : (decay * c + xv);
        buf[a] = c;
    }
    __syncthreads();
    float* oc = o_cal + (size_t)n * Tt;
    float* of = o_fl + (size_t)n * Tt;
    for (int i = tid; i < Tt; i += 256) {
        float cv = buf[(i & 63) * 257 + (i >> 6)];
        oc[i] = cv;
        of[i] = fscale * cv + fshift;
    }
}

// ---------------------------------------------------------------------------
extern "C" void kernel_launch(void* const* d_in, const int* in_sizes, int n_in,
                              void* d_out, int out_size)
{
    const float* fr    = (const float*)d_in[0];   // (N, WIN)
    const float* ffull = (const float*)d_in[1];   // (N, T)
    const float* odor  = (const float*)d_in[2];   // (T, 16)
    const float* mask  = (const float*)d_in[3];
    const float* Wenc  = (const float*)d_in[4];
    const float* benc  = (const float*)d_in[5];
    const float* Amu   = (const float*)d_in[6];
    const float* Bmu   = (const float*)d_in[7];
    const float* Alv   = (const float*)d_in[8];
    const float* Blv   = (const float*)d_in[9];
    const float* eps   = (const float*)d_in[10];
    const float* Wc    = (const float*)d_in[11];
    const float* We    = (const float*)d_in[12];
    const float* nbias = (const float*)d_in[13];
    const float* ntau  = (const float*)d_in[14];
    const float* aw    = (const float*)d_in[15];
    const float* ab    = (const float*)d_in[16];
    const float* fls   = (const float*)d_in[17];
    const float* flsh  = (const float*)d_in[18];
    const float* ctau  = (const float*)d_in[19];

    float* out = (float*)d_out;
    const size_t NT = (size_t)Nn * Tt;
    float* o_muv    = out + 0 * NT;   // mu_v_prob
    float* o_fl     = out + 1 * NT;   // mu_fluorescence
    float* o_mulat  = out + 2 * NT;   // mu_lat
    float* o_lvlat  = out + 3 * NT;   // lv_lat
    float* o_sample = out + 4 * NT;   // sample
    float* o_ca     = out + 5 * NT;   // calcium_activation
    float* o_cal    = out + 6 * NT;   // mu_calcium_prob
    float* o_rec    = out + 7 * NT;   // recurrent_in
    float* o_S      = out + 8 * NT;   // sensory_input

    float *gmu, *glv;
    cudaGetSymbolAddress((void**)&gmu, g_Gmu);
    cudaGetSymbolAddress((void**)&glv, g_Glv);

    // K0: sensory input
    k_sensory<<<dim3(Tt / 256, Nn), 256>>>(odor, Wenc, benc, mask, o_S);

    const int MB = (Nn + BM - 1) / BM;  // 5

    // K1a: G_mu = A_mu @ fr, G_lv = A_lv @ fr  (cols = WIN)
    k_gemm<0><<<dim3(WINw / BT, MB), 256>>>(
        Amu, Alv, fr, WINw, WINw,
        nullptr, nullptr, nullptr, nullptr, nullptr,
        nullptr, nullptr, nullptr, nullptr,
        gmu, glv, nullptr);

    // K1b: mu_lat/lv_lat/sample  (cols = T, X = S)
    k_gemm<1><<<dim3(Tt / BT, MB), 256>>>(
        Bmu, Blv, o_S, Tt, Tt,
        gmu, glv, eps, nullptr, nullptr,
        nullptr, nullptr, nullptr, nullptr,
        o_mulat, o_lvlat, o_sample);

    // K2: recurrent_in / mu_v_prob / calcium_activation  (X = sample)
    k_gemm<2><<<dim3(Tt / BT, MB), 256>>>(
        Wc, We, o_sample, Tt, Tt,
        nullptr, nullptr, nullptr, o_sample, o_S,
        ntau, nbias, aw, ab,
        o_rec, o_muv, o_ca);

    // K3: calcium scan + fluorescence
    const int scan_smem = 64 * 257 * 4;
    cudaFuncSetAttribute(k_scan, cudaFuncAttributeMaxDynamicSharedMemorySize,
                         scan_smem);
    k_scan<<<Nn, 256, scan_smem>>>(o_ca, ffull, fls, flsh, ctau, o_cal, o_fl);
}

// round 2
// speedup vs baseline: 1.1104x; 1.1104x over previous
#include <cuda_runtime.h>
#include <math.h>

#define Nn   300
#define Tt   16384
#define WINw 1024
#define ODORo 16
#define DTc  0.2f

#define BM 64
#define BT 128
#define BK 16
#define WPAD 68

// scratch: G = A_mu @ fr, A_lv @ fr (300 x 1024 each), sparse-K index list
__device__ float g_Gmu[Nn * WINw];
__device__ float g_Glv[Nn * WINw];
__device__ int   g_idx[Nn];
__device__ int   g_cnt;

// ---------------------------------------------------------------------------
// K0: sensory_input S[n,t] = mask[n] * (dot(odor[t,:], W_enc[n,:]) + b_enc[n])
// ---------------------------------------------------------------------------
__global__ void k_sensory(const float* __restrict__ odor,
                          const float* __restrict__ Wenc,
                          const float* __restrict__ benc,
                          const float* __restrict__ mask,
                          float* __restrict__ S)
{
    int t = blockIdx.x * blockDim.x + threadIdx.x;
    int n = blockIdx.y;
    if (t >= Tt) return;
    float w[ODORo];
#pragma unroll
    for (int k = 0; k < ODORo; k++) w[k] = __ldg(&Wenc[n * ODORo + k]);
    float acc = __ldg(&benc[n]);
    const float* orow = odor + (size_t)t * ODORo;
#pragma unroll
    for (int k = 0; k < ODORo; k++) acc += orow[k] * w[k];
    S[(size_t)n * Tt + t] = acc * __ldg(&mask[n]);
}

// ---------------------------------------------------------------------------
// K0b: compact nonzero-mask indices (exact sparse-K for B@S GEMMs).
// One block, 512 threads, Hillis-Steele scan.
// ---------------------------------------------------------------------------
__global__ void k_compact(const float* __restrict__ mask)
{
    __shared__ int ps[512];
    int tid = threadIdx.x;
    int p = (tid < Nn && mask[tid] != 0.0f) ? 1 : 0;
    ps[tid] = p;
    __syncthreads();
#pragma unroll
    for (int off = 1; off < 512; off <<= 1) {
        int v = ps[tid];
        if (tid >= off) v += ps[tid - off];
        __syncthreads();
        ps[tid] = v;
        __syncthreads();
    }
    if (p) g_idx[ps[tid] - 1] = tid;
    if (tid == 511) g_cnt = ps[511];
}

// ---------------------------------------------------------------------------
// Fused dual GEMM: C1 = W1 @ X, C2 = W2 @ X over the same X tile.
// Thread tile 4 rows x 8 cols -> 64 FFMA per k-step vs 4 LDS.128.
// MODE 0: oa=C1, ob=C2 (raw)
// MODE 1 (SPARSE): K runs over compacted nonzero-mask rows of S (exact).
//   mu=C1+Gmu[m,t>>4]; lv=C2+Glv[m,t>>4]; sample=mu+exp(.5lv)*eps
// MODE 2: rec = W_c@relu(X)+W_e@X; mu_v; calcium_activation (softplus)
// ---------------------------------------------------------------------------
template <int MODE, bool SPARSE>
__global__ __launch_bounds__(256, 2)
void k_gemm2(const float* __restrict__ W1,
             const float* __restrict__ W2,
             const float* __restrict__ X, int xstride, int tcols,
             const float* __restrict__ gmu,
             const float* __restrict__ glv,
             const float* __restrict__ eps,
             const float* __restrict__ sample,
             const float* __restrict__ S,
             const float* __restrict__ tau,
             const float* __restrict__ bias,
             const float* __restrict__ aw,
             const float* __restrict__ ab,
             float* __restrict__ oa,
             float* __restrict__ ob,
             float* __restrict__ oc)
{
    __shared__ __align__(16) float W1s[BK][WPAD];
    __shared__ __align__(16) float W2s[BK][WPAD];
    __shared__ __align__(16) float Xs[BK][BT];

    const int tid = threadIdx.x;          // 256
    const int tx = tid & 15;              // col group (8 cols)
    const int ty = tid >> 4;              // row group (4 rows)
    const int t0 = blockIdx.x * BT;
    const int m0 = blockIdx.y * BM;

    const int Klen = SPARSE ? g_cnt : Nn;

    // loader roles
    const int wm = tid >> 2;              // 0..63 : W row
    const int wk = (tid & 3) * 4;         // 0,4,8,12 : W k-quad
    const int xk = tid >> 4;              // 0..15 : X k-row
    const int xt = (tid & 15) * 8;        // X t offset

    float acc1[4][8] = {{0}}, acc2[4][8] = {{0}};

    for (int kk = 0; kk < Klen; kk += BK) {
        // ---- W tiles -> smem transposed [k][m]
        {
            int gm = m0 + wm;
            float w1v[4] = {0, 0, 0, 0}, w2v[4] = {0, 0, 0, 0};
            if (gm < Nn) {
                if (SPARSE) {
#pragma unroll
                    for (int i = 0; i < 4; i++) {
                        int kg = kk + wk + i;
                        if (kg < Klen) {
                            int col = g_idx[kg];
                            w1v[i] = W1[(size_t)gm * Nn + col];
                            w2v[i] = W2[(size_t)gm * Nn + col];
                        }
                    }
                } else if (kk + wk < Nn) {   // 300%4==0: float4 never straddles
                    float4 a = *(const float4*)&W1[(size_t)gm * Nn + kk + wk];
                    float4 b = *(const float4*)&W2[(size_t)gm * Nn + kk + wk];
                    w1v[0] = a.x; w1v[1] = a.y; w1v[2] = a.z; w1v[3] = a.w;
                    w2v[0] = b.x; w2v[1] = b.y; w2v[2] = b.z; w2v[3] = b.w;
                }
            }
#pragma unroll
            for (int i = 0; i < 4; i++) {
                W1s[wk + i][wm] = w1v[i];
                W2s[wk + i][wm] = w2v[i];
            }
        }
        // ---- X tile [k][t]
        {
            float4 v0 = make_float4(0, 0, 0, 0), v1 = v0;
            int kg = kk + xk;
            int row = -1;
            if (SPARSE) { if (kg < Klen) row = g_idx[kg]; }
            else        { if (kg < Nn)   row = kg; }
            if (row >= 0) {
                const float* xp = X + (size_t)row * xstride + t0 + xt;
                v0 = *(const float4*)xp;
                v1 = *(const float4*)(xp + 4);
            }
            *(float4*)&Xs[xk][xt]     = v0;
            *(float4*)&Xs[xk][xt + 4] = v1;
        }
        __syncthreads();

#pragma unroll
        for (int k = 0; k < BK; k++) {
            float4 a1q = *(const float4*)&W1s[k][ty * 4];
            float4 a2q = *(const float4*)&W2s[k][ty * 4];
            float4 x0 = *(const float4*)&Xs[k][tx * 8];
            float4 x1 = *(const float4*)&Xs[k][tx * 8 + 4];
            float xb[8] = {x0.x, x0.y, x0.z, x0.w, x1.x, x1.y, x1.z, x1.w};
            float a1v[4] = {a1q.x, a1q.y, a1q.z, a1q.w};
            float a2v[4] = {a2q.x, a2q.y, a2q.z, a2q.w};
            if (MODE == 2) {
                float xr[8];
#pragma unroll
                for (int j = 0; j < 8; j++) xr[j] = fmaxf(xb[j], 0.f);
#pragma unroll
                for (int i = 0; i < 4; i++)
#pragma unroll
                    for (int j = 0; j < 8; j++) {
                        acc1[i][j] += a1v[i] * xr[j];
                        acc2[i][j] += a2v[i] * xb[j];
                    }
            } else {
#pragma unroll
                for (int i = 0; i < 4; i++)
#pragma unroll
                    for (int j = 0; j < 8; j++) {
                        acc1[i][j] += a1v[i] * xb[j];
                        acc2[i][j] += a2v[i] * xb[j];
                    }
            }
        }
        __syncthreads();
    }

    // ---- epilogue (cols t0 + tx*8 .. +7 are contiguous; t>>4 constant/row)
#pragma unroll
    for (int i = 0; i < 4; i++) {
        int m = m0 + ty * 4 + i;
        if (m < Nn) {
            size_t ro = (size_t)m * tcols + t0 + tx * 8;
            if (MODE == 0) {
                *(float4*)&oa[ro]     = make_float4(acc1[i][0], acc1[i][1], acc1[i][2], acc1[i][3]);
                *(float4*)&oa[ro + 4] = make_float4(acc1[i][4], acc1[i][5], acc1[i][6], acc1[i][7]);
                *(float4*)&ob[ro]     = make_float4(acc2[i][0], acc2[i][1], acc2[i][2], acc2[i][3]);
                *(float4*)&ob[ro + 4] = make_float4(acc2[i][4], acc2[i][5], acc2[i][6], acc2[i][7]);
            } else if (MODE == 1) {
                size_t gi = (size_t)m * WINw + ((t0 + tx * 8) >> 4);
                float gm = gmu[gi], gl = glv[gi];
                float4 e0 = *(const float4*)&eps[ro];
                float4 e1 = *(const float4*)&eps[ro + 4];
                float ev[8] = {e0.x, e0.y, e0.z, e0.w, e1.x, e1.y, e1.z, e1.w};
                float mu[8], lv[8], sm[8];
#pragma unroll
                for (int j = 0; j < 8; j++) {
                    mu[j] = acc1[i][j] + gm;
                    lv[j] = acc2[i][j] + gl;
                    sm[j] = mu[j] + expf(0.5f * lv[j]) * ev[j];
                }
                *(float4*)&oa[ro]     = make_float4(mu[0], mu[1], mu[2], mu[3]);
                *(float4*)&oa[ro + 4] = make_float4(mu[4], mu[5], mu[6], mu[7]);
                *(float4*)&ob[ro]     = make_float4(lv[0], lv[1], lv[2], lv[3]);
                *(float4*)&ob[ro + 4] = make_float4(lv[4], lv[5], lv[6], lv[7]);
                *(float4*)&oc[ro]     = make_float4(sm[0], sm[1], sm[2], sm[3]);
                *(float4*)&oc[ro + 4] = make_float4(sm[4], sm[5], sm[6], sm[7]);
            } else {
                float alpha = DTc / fmaxf(__ldg(&tau[m]), DTc);
                float bi = __ldg(&bias[m]);
                float awm = __ldg(&aw[m]), abm = __ldg(&ab[m]);
                float4 s0 = *(const float4*)&sample[ro];
                float4 s1 = *(const float4*)&sample[ro + 4];
                float4 q0 = *(const float4*)&S[ro];
                float4 q1 = *(const float4*)&S[ro + 4];
                float sv[8] = {s0.x, s0.y, s0.z, s0.w, s1.x, s1.y, s1.z, s1.w};
                float qv[8] = {q0.x, q0.y, q0.z, q0.w, q1.x, q1.y, q1.z, q1.w};
                float rec[8], muv[8], ca[8];
#pragma unroll
                for (int j = 0; j < 8; j++) {
                    rec[j] = acc1[i][j] + acc2[i][j];
                    muv[j] = sv[j] + alpha * (rec[j] - sv[j] + qv[j] + bi);
                    float z = awm * sv[j] + abm;
                    ca[j] = fmaxf(z, 0.f) + log1pf(expf(-fabsf(z)));
                }
                *(float4*)&oa[ro]     = make_float4(rec[0], rec[1], rec[2], rec[3]);
                *(float4*)&oa[ro + 4] = make_float4(rec[4], rec[5], rec[6], rec[7]);
                *(float4*)&ob[ro]     = make_float4(muv[0], muv[1], muv[2], muv[3]);
                *(float4*)&ob[ro + 4] = make_float4(muv[4], muv[5], muv[6], muv[7]);
                *(float4*)&oc[ro]     = make_float4(ca[0], ca[1], ca[2], ca[3]);
                *(float4*)&oc[ro + 4] = make_float4(ca[4], ca[5], ca[6], ca[7]);
            }
        }
    }
}

// ---------------------------------------------------------------------------
// K3: exponential calcium filter. decay=e^-1 (tau clipped to DT) => 64-step
// lookback reconstructs carry to <1e-27 rel. smem transposed [64][257].
// ---------------------------------------------------------------------------
__global__ void k_scan(const float* __restrict__ ca,
                       const float* __restrict__ ffull,
                       const float* __restrict__ fls,
                       const float* __restrict__ flsh,
                       const float* __restrict__ ctau,
                       float* __restrict__ o_cal,
                       float* __restrict__ o_fl)
{
    extern __shared__ float buf[];
    const int n = blockIdx.x;
    const int tid = threadIdx.x;
    const int C = Tt / 256;  // 64

    const float* x = ca + (size_t)n * Tt;
    for (int i = tid; i < Tt; i += 256)
        buf[(i & 63) * 257 + (i >> 6)] = x[i];

    float fscale = __ldg(&fls[n]);
    float fshift = __ldg(&flsh[n]);
    float init = (__ldg(&ffull[(size_t)n * Tt]) - fshift) / fscale;
    float decay = expf(-DTc / fmaxf(__ldg(&ctau[n]), DTc));
    __syncthreads();

    const int start = tid * C;
    int lb = start - 64;
    float c;
    int s0;
    if (lb <= 0) { c = init; s0 = 0; }
    else         { c = 0.f;  s0 = lb; }
    for (int s = s0; s < start; s++) {
        float xv = buf[(s & 63) * 257 + (s >> 6)];
        c = (s == 0) ? (c + xv) : (decay * c + xv);
    }
    __syncthreads();
    for (int t = start; t < start + C; t++) {
        int a = (t & 63) * 257 + (t >> 6);
        float xv = buf[a];
        c = (t == 0) ? (c + xv) : (decay * c + xv);
        buf[a] = c;
    }
    __syncthreads();
    float* ocp = o_cal + (size_t)n * Tt;
    float* ofp = o_fl + (size_t)n * Tt;
    for (int i = tid; i < Tt; i += 256) {
        float cv = buf[(i & 63) * 257 + (i >> 6)];
        ocp[i] = cv;
        ofp[i] = fscale * cv + fshift;
    }
}

// ---------------------------------------------------------------------------
extern "C" void kernel_launch(void* const* d_in, const int* in_sizes, int n_in,
                              void* d_out, int out_size)
{
    const float* fr    = (const float*)d_in[0];
    const float* ffull = (const float*)d_in[1];
    const float* odor  = (const float*)d_in[2];
    const float* mask  = (const float*)d_in[3];
    const float* Wenc  = (const float*)d_in[4];
    const float* benc  = (const float*)d_in[5];
    const float* Amu   = (const float*)d_in[6];
    const float* Bmu   = (const float*)d_in[7];
    const float* Alv   = (const float*)d_in[8];
    const float* Blv   = (const float*)d_in[9];
    const float* eps   = (const float*)d_in[10];
    const float* Wc    = (const float*)d_in[11];
    const float* We    = (const float*)d_in[12];
    const float* nbias = (const float*)d_in[13];
    const float* ntau  = (const float*)d_in[14];
    const float* aw    = (const float*)d_in[15];
    const float* ab    = (const float*)d_in[16];
    const float* fls   = (const float*)d_in[17];
    const float* flsh  = (const float*)d_in[18];
    const float* ctau  = (const float*)d_in[19];

    float* out = (float*)d_out;
    const size_t NT = (size_t)Nn * Tt;
    float* o_muv    = out + 0 * NT;
    float* o_fl     = out + 1 * NT;
    float* o_mulat  = out + 2 * NT;
    float* o_lvlat  = out + 3 * NT;
    float* o_sample = out + 4 * NT;
    float* o_ca     = out + 5 * NT;
    float* o_cal    = out + 6 * NT;
    float* o_rec    = out + 7 * NT;
    float* o_S      = out + 8 * NT;

    float *gmu, *glv;
    cudaGetSymbolAddress((void**)&gmu, g_Gmu);
    cudaGetSymbolAddress((void**)&glv, g_Glv);

    k_sensory<<<dim3(Tt / 256, Nn), 256>>>(odor, Wenc, benc, mask, o_S);
    k_compact<<<1, 512>>>(mask);

    const int MB = (Nn + BM - 1) / BM;  // 5

    // K1a: G_mu = A_mu @ fr, G_lv = A_lv @ fr (dense K, cols=WIN)
    k_gemm2<0, false><<<dim3(WINw / BT, MB), 256>>>(
        Amu, Alv, fr, WINw, WINw,
        nullptr, nullptr, nullptr, nullptr, nullptr,
        nullptr, nullptr, nullptr, nullptr,
        gmu, glv, nullptr);

    // K1b: mu_lat/lv_lat/sample (sparse K over nonzero mask rows of S)
    k_gemm2<1, true><<<dim3(Tt / BT, MB), 256>>>(
        Bmu, Blv, o_S, Tt, Tt,
        gmu, glv, eps, nullptr, nullptr,
        nullptr, nullptr, nullptr, nullptr,
        o_mulat, o_lvlat, o_sample);

    // K2: recurrent_in / mu_v_prob / calcium_activation (dense)
    k_gemm2<2, false><<<dim3(Tt / BT, MB), 256>>>(
        Wc, We, o_sample, Tt, Tt,
        nullptr, nullptr, nullptr, o_sample, o_S,
        ntau, nbias, aw, ab,
        o_rec, o_muv, o_ca);

    const int scan_smem = 64 * 257 * 4;
    cudaFuncSetAttribute(k_scan, cudaFuncAttributeMaxDynamicSharedMemorySize,
                         scan_smem);
    k_scan<<<Nn, 256, scan_smem>>>(o_ca, ffull, fls, flsh, ctau, o_cal, o_fl);
}